// round 1
// baseline (speedup 1.0000x reference)
#include <cuda_runtime.h>
#include <math.h>

#define FH 50
#define FW 50
#define NPOS 2500
#define CIN 256
#define CMID 512
#define KDIM 2304          // 256*9
#define APER 9
#define NANCH 22500        // 2500*9
#define NSORT 32768
#define NPRE 6000
#define NPOST 300
#define NWORDS 94          // ceil(6000/64)
#define NMS_T 0.7f
#define MINSZ 16.0f

// ---------------- scratch (device globals; zero-initialized once) ----------------
__device__ float g_h[2 * CMID * NPOS];                 // conv1 output (relu)
__device__ __align__(16) float g_boxes[2 * NANCH * 4]; // decoded boxes
__device__ float g_scores[2 * NANCH];                  // filtered scores (or -1)
__device__ unsigned long long g_keys[2 * NSORT];       // sort keys
__device__ __align__(16) float g_boxes6k[2 * NPRE * 4];
__device__ float g_scores6k[2 * NPRE];
__device__ unsigned long long g_mask[(size_t)2 * NPRE * NWORDS]; // only words >= row-chunk ever written

// ---------------- conv 3x3 (implicit GEMM, fp32) ----------------
// M=512 (co), N=2500 (spatial), K=2304.  BM=BN=64, BK=16, 256 thr, 4x4 per thread.
__global__ __launch_bounds__(256) void conv3x3_kernel(
    const float* __restrict__ x, const float* __restrict__ w, const float* __restrict__ bias)
{
    const int b   = blockIdx.z;
    const int co0 = blockIdx.y * 64;
    const int n0  = blockIdx.x * 64;
    const int t   = threadIdx.x;

    __shared__ __align__(16) float As[16][68];
    __shared__ __align__(16) float Bs[16][68];

    float acc[4][4];
#pragma unroll
    for (int i = 0; i < 4; i++)
#pragma unroll
        for (int j = 0; j < 4; j++) acc[i][j] = 0.f;

    const int tx = t & 15, ty = t >> 4;
    const int rowA = t >> 2;            // 0..63
    const int kcA  = (t & 3) * 4;       // 0,4,8,12
    const int kB   = t >> 4;            // 0..15
    const int nB   = (t & 15) * 4;      // 0..60

    const float* wrow = w + (size_t)(co0 + rowA) * KDIM;
    const float* xb   = x + (size_t)b * CIN * NPOS;

    for (int kt = 0; kt < KDIM / 16; ++kt) {
        const int k0 = kt * 16;
        // A tile
        float4 av = *(const float4*)(wrow + k0 + kcA);
        As[kcA + 0][rowA] = av.x;
        As[kcA + 1][rowA] = av.y;
        As[kcA + 2][rowA] = av.z;
        As[kcA + 3][rowA] = av.w;
        // B tile (im2col on the fly)
        {
            const int k  = k0 + kB;
            const int ci = k / 9;
            const int r  = k - ci * 9;
            const int ky = r / 3, kx = r - ky * 3;
            const float* xp = xb + (size_t)ci * NPOS;
#pragma unroll
            for (int u = 0; u < 4; u++) {
                const int n = n0 + nB + u;
                float v = 0.f;
                if (n < NPOS) {
                    const int y  = n / FW;
                    const int xx = n - y * FW;
                    const int iy = y + ky - 1, ix = xx + kx - 1;
                    if (iy >= 0 && iy < FH && ix >= 0 && ix < FW) v = xp[iy * FW + ix];
                }
                Bs[kB][nB + u] = v;
            }
        }
        __syncthreads();
#pragma unroll
        for (int kk = 0; kk < 16; kk++) {
            const float4 af = *(const float4*)&As[kk][ty * 4];
            const float4 bf = *(const float4*)&Bs[kk][tx * 4];
            const float ar[4] = {af.x, af.y, af.z, af.w};
            const float br[4] = {bf.x, bf.y, bf.z, bf.w};
#pragma unroll
            for (int i = 0; i < 4; i++)
#pragma unroll
                for (int j = 0; j < 4; j++) acc[i][j] += ar[i] * br[j];
        }
        __syncthreads();
    }

#pragma unroll
    for (int i = 0; i < 4; i++) {
        const int co = co0 + ty * 4 + i;
        const float bv = bias[co];
        float* hp = g_h + ((size_t)(b * CMID + co)) * NPOS;
#pragma unroll
        for (int j = 0; j < 4; j++) {
            const int n = n0 + tx * 4 + j;
            if (n < NPOS) {
                float v = acc[i][j] + bv;
                hp[n] = v > 0.f ? v : 0.f;
            }
        }
    }
}

// ---------------- heads: 1x1 convs + softmax + decode + key ----------------
__device__ __forceinline__ float to_dim(const int* p) {
    int v = *p;
    if (v > 0 && v < 100000) return (float)v;
    return __int_as_float(v);
}

__global__ __launch_bounds__(256) void heads_kernel(
    const float* __restrict__ ow, const float* __restrict__ ob,
    const float* __restrict__ lw, const float* __restrict__ lb,
    const float* __restrict__ anchors, const int* ihp, const int* iwp)
{
    const int b  = blockIdx.y;
    const int n0 = blockIdx.x * 16;
    const int t  = threadIdx.x;

    __shared__ float hs[CMID][17];
    __shared__ float outs[54][16];

    // load h tile [512][16]
    for (int idx = t; idx < CMID * 16; idx += 256) {
        const int c = idx >> 4, i = idx & 15;
        const int n = n0 + i;
        hs[c][i] = (n < NPOS) ? g_h[((size_t)(b * CMID + c)) * NPOS + n] : 0.f;
    }
    __syncthreads();

    // compute 54 head channels
    {
        const int i = t & 15, g = t >> 4;
        float acc[4] = {0.f, 0.f, 0.f, 0.f};
        const float* wp[4];
        float bs[4];
#pragma unroll
        for (int s = 0; s < 4; s++) {
            const int oc = g + s * 16;
            if (oc < 18)       { wp[s] = ow + oc * CMID;        bs[s] = ob[oc]; }
            else if (oc < 54)  { wp[s] = lw + (oc - 18) * CMID; bs[s] = lb[oc - 18]; }
            else               { wp[s] = ow;                    bs[s] = 0.f; }
        }
#pragma unroll 4
        for (int c = 0; c < CMID; c++) {
            const float v = hs[c][i];
            acc[0] += wp[0][c] * v;
            acc[1] += wp[1][c] * v;
            acc[2] += wp[2][c] * v;
            acc[3] += wp[3][c] * v;
        }
#pragma unroll
        for (int s = 0; s < 4; s++) {
            const int oc = g + s * 16;
            if (oc < 54) outs[oc][i] = acc[s] + bs[s];
        }
    }
    __syncthreads();

    // anchors: 9 per position
    if (t < 144) {
        const int i = t & 15, a = t >> 4;
        const int n = n0 + i;
        if (n < NPOS) {
            const float imgw = to_dim(iwp), imgh = to_dim(ihp);
            const int m = n * APER + a;
            const float o0 = outs[2 * a][i], o1 = outs[2 * a + 1][i];
            const float mx = fmaxf(o0, o1);
            const float e0 = expf(o0 - mx), e1 = expf(o1 - mx);
            const float sc = e1 / (e0 + e1);

            const float l0 = outs[18 + 4 * a + 0][i];
            const float l1 = outs[18 + 4 * a + 1][i];
            const float l2 = outs[18 + 4 * a + 2][i];
            const float l3 = outs[18 + 4 * a + 3][i];

            const float a0 = anchors[m * 4 + 0], a1 = anchors[m * 4 + 1];
            const float a2 = anchors[m * 4 + 2], a3 = anchors[m * 4 + 3];
            const float aw = a2 - a0, ah = a3 - a1;
            const float acx = a0 + 0.5f * aw, acy = a1 + 0.5f * ah;
            const float cx = acx + l0 * aw, cy = acy + l1 * ah;
            const float wd = aw * expf(l2), hh = ah * expf(l3);
            float x1 = fminf(fmaxf(cx - 0.5f * wd, 0.f), imgw);
            float y1 = fminf(fmaxf(cy - 0.5f * hh, 0.f), imgh);
            float x2 = fminf(fmaxf(cx + 0.5f * wd, 0.f), imgw);
            float y2 = fminf(fmaxf(cy + 0.5f * hh, 0.f), imgh);

            const bool valid = (x2 - x1 >= MINSZ) && (y2 - y1 >= MINSZ);
            const float s2 = valid ? sc : -1.f;

            float* bp = g_boxes + ((size_t)(b * NANCH + m)) * 4;
            bp[0] = x1; bp[1] = y1; bp[2] = x2; bp[3] = y2;
            g_scores[b * NANCH + m] = s2;

            const unsigned sb = __float_as_uint(s2);
            const unsigned mono = (sb & 0x80000000u) ? ~sb : (sb | 0x80000000u);
            g_keys[b * NSORT + m] =
                ((unsigned long long)mono << 32) |
                (unsigned long long)(0xFFFFFFFFu - (unsigned)m);
        }
    }
}

// ---------------- pad sort keys ----------------
__global__ void pad_keys_kernel() {
    const int per = NSORT - NANCH;
    const int t = blockIdx.x * blockDim.x + threadIdx.x;
    if (t < 2 * per) {
        const int b = t / per, r = t - b * per;
        g_keys[b * NSORT + NANCH + r] = 0ull;
    }
}

// ---------------- bitonic sort (descending), 2 independent 32768 segments ----------------
__device__ __forceinline__ void bit_cmp(unsigned long long& ki, unsigned long long& kp, bool up) {
    const bool sw = up ? (ki < kp) : (ki > kp);
    if (sw) { unsigned long long tmp = ki; ki = kp; kp = tmp; }
}

__global__ __launch_bounds__(512) void bitonic_local_sort() {
    __shared__ unsigned long long sk[4096];
    const int seg   = blockIdx.x >> 3;         // batch
    const int chunk = blockIdx.x & 7;
    const int base  = seg * NSORT + chunk * 4096;
    const int gbase = chunk * 4096;
    for (int i = threadIdx.x; i < 4096; i += 512) sk[i] = g_keys[base + i];
    __syncthreads();
    for (int k = 2; k <= 4096; k <<= 1) {
        for (int j = k >> 1; j > 0; j >>= 1) {
#pragma unroll
            for (int s = 0; s < 4; s++) {
                const int c = threadIdx.x + s * 512;
                const int i = 2 * j * (c / j) + (c % j);
                const int p = i + j;
                const bool up = (((gbase + i) & k) == 0);
                unsigned long long ki = sk[i], kp = sk[p];
                bit_cmp(ki, kp, up);
                sk[i] = ki; sk[p] = kp;
            }
            __syncthreads();
        }
    }
    for (int i = threadIdx.x; i < 4096; i += 512) g_keys[base + i] = sk[i];
}

__global__ void bitonic_global(int k, int j) {
    const int tid = blockIdx.x * blockDim.x + threadIdx.x;
    if (tid >= 2 * (NSORT / 2)) return;
    const int seg = tid >> 14;
    const int c   = tid & 16383;
    const int i   = 2 * j * (c / j) + (c % j);
    const int p   = i + j;
    unsigned long long* kb = g_keys + seg * NSORT;
    const bool up = ((i & k) == 0);
    unsigned long long ki = kb[i], kp = kb[p];
    const bool sw = up ? (ki < kp) : (ki > kp);
    if (sw) { kb[i] = kp; kb[p] = ki; }
}

__global__ __launch_bounds__(512) void bitonic_merge_local(int k) {
    __shared__ unsigned long long sk[4096];
    const int seg   = blockIdx.x >> 3;
    const int chunk = blockIdx.x & 7;
    const int base  = seg * NSORT + chunk * 4096;
    const int gbase = chunk * 4096;
    for (int i = threadIdx.x; i < 4096; i += 512) sk[i] = g_keys[base + i];
    __syncthreads();
    for (int j = 2048; j > 0; j >>= 1) {
#pragma unroll
        for (int s = 0; s < 4; s++) {
            const int c = threadIdx.x + s * 512;
            const int i = 2 * j * (c / j) + (c % j);
            const int p = i + j;
            const bool up = (((gbase + i) & k) == 0);
            unsigned long long ki = sk[i], kp = sk[p];
            bit_cmp(ki, kp, up);
            sk[i] = ki; sk[p] = kp;
        }
        __syncthreads();
    }
    for (int i = threadIdx.x; i < 4096; i += 512) g_keys[base + i] = sk[i];
}

// ---------------- gather top-6000 ----------------
__global__ void gather_top() {
    const int tid = blockIdx.x * blockDim.x + threadIdx.x;
    if (tid >= 2 * NPRE) return;
    const int b = tid / NPRE, r = tid - b * NPRE;
    const unsigned long long key = g_keys[b * NSORT + r];
    const unsigned idx = 0xFFFFFFFFu - (unsigned)(key & 0xFFFFFFFFull);
    const float* src = g_boxes + ((size_t)(b * NANCH + idx)) * 4;
    float* dst = g_boxes6k + ((size_t)(b * NPRE + r)) * 4;
    dst[0] = src[0]; dst[1] = src[1]; dst[2] = src[2]; dst[3] = src[3];
    g_scores6k[b * NPRE + r] = g_scores[b * NANCH + idx];
}

// ---------------- NMS suppression masks ----------------
__global__ __launch_bounds__(64) void nms_mask_kernel() {
    const int cb = blockIdx.x, rb = blockIdx.y, b = blockIdx.z;
    if (cb < rb) return;
    __shared__ float4 cbox[64];
    __shared__ float carea[64];
    const int t = threadIdx.x;
    const int j0 = cb * 64 + t;
    if (j0 < NPRE) {
        float4 v = *(const float4*)&g_boxes6k[((size_t)(b * NPRE + j0)) * 4];
        cbox[t] = v;
        carea[t] = (v.z - v.x) * (v.w - v.y);
    }
    __syncthreads();
    const int i = rb * 64 + t;
    if (i >= NPRE) return;
    const float4 bi = *(const float4*)&g_boxes6k[((size_t)(b * NPRE + i)) * 4];
    const float ai = (bi.z - bi.x) * (bi.w - bi.y);
    unsigned long long bits = 0ull;
    const int jmax = min(64, NPRE - cb * 64);
    for (int jj = 0; jj < jmax; jj++) {
        const int jg = cb * 64 + jj;
        if (jg <= i) continue;
        const float4 bj = cbox[jj];
        const float ix1 = fmaxf(bi.x, bj.x), iy1 = fmaxf(bi.y, bj.y);
        const float ix2 = fminf(bi.z, bj.z), iy2 = fminf(bi.w, bj.w);
        const float inter = fmaxf(ix2 - ix1, 0.f) * fmaxf(iy2 - iy1, 0.f);
        const float iou = inter / (ai + carea[jj] - inter);
        if (iou > NMS_T) bits |= 1ull << jj;
    }
    g_mask[((size_t)(b * NPRE + i)) * NWORDS + cb] = bits;
}

// ---------------- sequential selection + output ----------------
__global__ __launch_bounds__(128) void select_out_kernel(float* __restrict__ out) {
    const int b = blockIdx.x;
    const int t = threadIdx.x;
    __shared__ unsigned long long removed[NWORDS];
    __shared__ int keep[NPOST];
    __shared__ int s_count;
    if (t < NWORDS) removed[t] = 0ull;
    if (t == 0) s_count = 0;
    __syncthreads();

    if (t < 32) {  // warp 0 does greedy selection
        const int lane = t;
        int count = 0;
        bool done = false;
        for (int c = 0; c < NWORDS && !done; c++) {
            unsigned long long live = 0ull;
            if (lane == 0) {
                live = ~removed[c];
                if (c == NWORDS - 1) live &= ((1ull << (NPRE - 64 * (NWORDS - 1))) - 1ull);
            }
            while (true) {
                int bitpos = -1;
                if (lane == 0) bitpos = live ? (__ffsll((long long)live) - 1) : -1;
                bitpos = __shfl_sync(0xffffffffu, bitpos, 0);
                if (bitpos < 0) break;
                const int idx = c * 64 + bitpos;
                const float sc = g_scores6k[b * NPRE + idx];
                if (sc < 0.f) { done = true; break; }
                if (lane == 0) keep[count] = idx;
                count++;
                if (count >= NPOST) { done = true; break; }
                const unsigned long long* mrow =
                    g_mask + ((size_t)(b * NPRE + idx)) * NWORDS;
                for (int wdx = lane; wdx < NWORDS; wdx += 32) removed[wdx] |= mrow[wdx];
                __syncwarp();
                if (lane == 0) {
                    live &= ~(1ull << bitpos);
                    live &= ~mrow[c];
                }
            }
        }
        if (lane == 0) s_count = count;
    }
    __syncthreads();

    const int cnt = s_count;
    for (int r = t; r < NPOST; r += 128) {
        float bx0 = 0.f, bx1 = 0.f, bx2 = 0.f, bx3 = 0.f, sv = 0.f, mv = 0.f;
        if (r < cnt) {
            const int i = keep[r];
            const float* bp = g_boxes6k + ((size_t)(b * NPRE + i)) * 4;
            bx0 = bp[0]; bx1 = bp[1]; bx2 = bp[2]; bx3 = bp[3];
            sv = g_scores6k[b * NPRE + i];
            mv = 1.f;
        }
        float* ob = out + b * (NPOST * 4) + r * 4;
        ob[0] = bx0; ob[1] = bx1; ob[2] = bx2; ob[3] = bx3;
        out[2 * NPOST * 4 + b * NPOST + r] = sv;
        out[2 * NPOST * 4 + 2 * NPOST + b * NPOST + r] = mv;
    }
}

// ---------------- launch ----------------
extern "C" void kernel_launch(void* const* d_in, const int* in_sizes, int n_in,
                              void* d_out, int out_size)
{
    const float* x   = (const float*)d_in[0];
    const float* c1w = (const float*)d_in[1];
    const float* c1b = (const float*)d_in[2];
    const float* ow  = (const float*)d_in[3];
    const float* ob  = (const float*)d_in[4];
    const float* lw  = (const float*)d_in[5];
    const float* lb  = (const float*)d_in[6];
    const float* anc = (const float*)d_in[7];
    const int*   ih  = (const int*)d_in[8];
    const int*   iw  = (const int*)d_in[9];
    float* out = (float*)d_out;

    conv3x3_kernel<<<dim3(40, 8, 2), 256>>>(x, c1w, c1b);
    heads_kernel<<<dim3(157, 2), 256>>>(ow, ob, lw, lb, anc, ih, iw);
    pad_keys_kernel<<<(2 * (NSORT - NANCH) + 255) / 256, 256>>>();

    bitonic_local_sort<<<16, 512>>>();
    bitonic_global<<<128, 256>>>(8192, 4096);
    bitonic_merge_local<<<16, 512>>>(8192);
    bitonic_global<<<128, 256>>>(16384, 8192);
    bitonic_global<<<128, 256>>>(16384, 4096);
    bitonic_merge_local<<<16, 512>>>(16384);
    bitonic_global<<<128, 256>>>(32768, 16384);
    bitonic_global<<<128, 256>>>(32768, 8192);
    bitonic_global<<<128, 256>>>(32768, 4096);
    bitonic_merge_local<<<16, 512>>>(32768);

    gather_top<<<(2 * NPRE + 255) / 256, 256>>>();
    nms_mask_kernel<<<dim3(NWORDS, NWORDS, 2), 64>>>();
    select_out_kernel<<<2, 128>>>(out);
}